// round 14
// baseline (speedup 1.0000x reference)
#include <cuda_runtime.h>
#include <cuda_fp16.h>
#include <cstdint>

// ---------------------------------------------------------------------------
//   x [2,2048,1024] f32, Wq/Wk/Wv [1024,1024] f32 ([k][n]), bq/bk/bv [1024]
//   out [2,2048,1024] f32 = causal MHA, 16 heads, head_dim 64,
//   softmax((QK^T + mask)/8)
// fp16 datapath: fp16 (10-bit mantissa) == tf32 precision for these ranges.
// NOTE: harness compiles at compute_103 (no 'a') -> tcgen05 unavailable;
// legacy mma.m16n8k16 is the MMA path.
// ---------------------------------------------------------------------------

#define NHEADS 16
#define HDIM   64
#define SEQ    2048
#define BATCH  2
#define DMODEL 1024

// fp16 pair-packed scratch (word = __half2 = 2 consecutive elements)
__device__ unsigned g_xh[4096 * 512];            // x  [m][k-words], permuted groups
__device__ unsigned g_wt[3 * 1024 * 512];        // W^T [mat][n][k-words], permuted
__device__ unsigned g_qh[BATCH * NHEADS * SEQ * 32];  // [b,h,s][dh-words], permuted
__device__ unsigned g_kh[BATCH * NHEADS * SEQ * 32];  // permuted
__device__ unsigned g_vh[BATCH * NHEADS * SEQ * 32];  // plain row-major (ldmatrix.trans)

// ---------------------------------------------------------------------------
// helpers — mma.m16n8k16 fp16, thread (g=lane>>2, tig=lane&3):
//   A row: a0=(g,2tig..+1) a1=(g+8,2tig..) a2=(g,2tig+8..) a3=(g+8,2tig+8..)
//   B col: b0=(k 2tig..+1, n g) b1=(k 2tig+8.., n g)
//   C:     c0=(g,2tig) c1=(g,2tig+1) c2=(g+8,2tig) c3=(g+8,2tig+1)
//   => QK C-frag (per nt) IS the PV A-frag k-pair: no smem round-trip for P.
//   Word perm within 8-word group: [0,4,1,5,2,6,3,7] -> (tig,tig+4) adjacent.
// ---------------------------------------------------------------------------
__device__ __forceinline__ int permc(int w) {  // w in [0,8)
    return ((w & 3) << 1) | (w >> 2);
}

__device__ __forceinline__ unsigned packh2(float lo, float hi) {
    __half2 h = __floats2half2_rn(lo, hi);
    return *(unsigned*)&h;
}

__device__ __forceinline__ void mma16(float& d0, float& d1, float& d2, float& d3,
                                      unsigned a0, unsigned a1, unsigned a2, unsigned a3,
                                      unsigned b0, unsigned b1) {
    asm("mma.sync.aligned.m16n8k16.row.col.f32.f16.f16.f32 "
        "{%0,%1,%2,%3},{%4,%5,%6,%7},{%8,%9},{%0,%1,%2,%3};"
        : "+f"(d0), "+f"(d1), "+f"(d2), "+f"(d3)
        : "r"(a0), "r"(a1), "r"(a2), "r"(a3), "r"(b0), "r"(b1));
}

// ldmatrix x4 transposed: 16k x 16n row-major b16 tile -> two B operands
__device__ __forceinline__ void ldmT4(unsigned& r0, unsigned& r1,
                                      unsigned& r2, unsigned& r3, const void* p) {
    unsigned a = (unsigned)__cvta_generic_to_shared(p);
    asm volatile("ldmatrix.sync.aligned.m8n8.x4.trans.shared.b16 {%0,%1,%2,%3}, [%4];"
                 : "=r"(r0), "=r"(r1), "=r"(r2), "=r"(r3) : "r"(a));
}

__device__ __forceinline__ void cp16(void* smem, const void* gmem) {
    unsigned s = (unsigned)__cvta_generic_to_shared(smem);
    asm volatile("cp.async.ca.shared.global [%0], [%1], 16;" :: "r"(s), "l"(gmem));
}
#define CP_COMMIT() asm volatile("cp.async.commit_group;" ::: "memory")

// ---------------------------------------------------------------------------
// Pre-pass: pack x -> fp16 pair-words, permuted within 16-elem groups
// ---------------------------------------------------------------------------
__global__ void pack_x_kernel(const float* __restrict__ x) {
    int idx = blockIdx.x * 256 + threadIdx.x;   // 262144 groups of 16 floats
    const float4* src = (const float4*)x + (size_t)idx * 4;
    float4 f0 = src[0], f1 = src[1], f2 = src[2], f3 = src[3];
    unsigned w0 = packh2(f0.x, f0.y), w1 = packh2(f0.z, f0.w);
    unsigned w2 = packh2(f1.x, f1.y), w3 = packh2(f1.z, f1.w);
    unsigned w4 = packh2(f2.x, f2.y), w5 = packh2(f2.z, f2.w);
    unsigned w6 = packh2(f3.x, f3.y), w7 = packh2(f3.z, f3.w);
    uint4* dst = (uint4*)(g_xh + (size_t)idx * 8);
    dst[0] = make_uint4(w0, w4, w1, w5);   // permuted order [0,4,1,5,2,6,3,7]
    dst[1] = make_uint4(w2, w6, w3, w7);
}

// Pre-pass: pack W^T -> g_wt[mat][n][k-words], pairs along k, permuted
__global__ void pack_w_kernel(const float* __restrict__ Wq,
                              const float* __restrict__ Wk,
                              const float* __restrict__ Wv) {
    int id  = blockIdx.x * 256 + threadIdx.x;   // 196608 = 3 * 1024n * 64grp
    int mat = id >> 16;
    int rem = id & 65535;
    int grp = rem >> 10;
    int n   = rem & 1023;
    const float* W = (mat == 0) ? Wq : ((mat == 1) ? Wk : Wv);
    int k0 = grp * 16;
    float f[16];
#pragma unroll
    for (int j = 0; j < 16; j++) f[j] = W[(size_t)(k0 + j) * DMODEL + n];
    unsigned w[8];
#pragma unroll
    for (int j = 0; j < 8; j++) w[j] = packh2(f[2 * j], f[2 * j + 1]);
    uint4* dst = (uint4*)(g_wt + ((size_t)mat << 19) + (size_t)n * 512 + grp * 8);
    dst[0] = make_uint4(w[0], w[4], w[1], w[5]);
    dst[1] = make_uint4(w[2], w[6], w[3], w[7]);
}

// ---------------------------------------------------------------------------
// Kernel 1: QKV projection, fp16 m16n8k16, cp.async double-buffered
//   grid (24, 32): x = mat*8 + ntile (BN=128), y = m-tile (BM=128), BK=32
//   8 warps 4(M)x2(N), warp tile 32x64
// ---------------------------------------------------------------------------
#define QA_STR 24   // 16 words + 8 pad: frag bank pattern conflict-free
#define QB_STR 24

__global__ __launch_bounds__(256, 2)
void qkv_h(const float* __restrict__ bq, const float* __restrict__ bk,
           const float* __restrict__ bv) {
    __shared__ unsigned As[2][128 * QA_STR];
    __shared__ unsigned Bs[2][128 * QB_STR];

    const int tid  = threadIdx.x;
    const int wid  = tid >> 5;
    const int lane = tid & 31;
    const int g    = lane >> 2;
    const int tig  = lane & 3;

    const int mat = blockIdx.x >> 3;
    const int n0  = (blockIdx.x & 7) * 128;
    const int m0  = blockIdx.y * 128;

    const unsigned* Asrc = g_xh + (size_t)m0 * 512;
    const unsigned* Bsrc = g_wt + ((size_t)mat << 19) + (size_t)n0 * 512;
    const float* bias = (mat == 0) ? bq : ((mat == 1) ? bk : bv);

    const int warpM = (wid & 3) * 32;
    const int warpN = (wid >> 2) * 64;

    float acc[2][8][4];
#pragma unroll
    for (int mt = 0; mt < 2; mt++)
#pragma unroll
        for (int nt = 0; nt < 8; nt++)
#pragma unroll
            for (int j = 0; j < 4; j++) acc[mt][nt][j] = 0.f;

    const int r0 = tid >> 2, c0 = (tid & 3) * 4;        // rows 0-63
    const int r1 = r0 + 64;                             // rows 64-127

    // prologue: stage tile 0
    cp16(&As[0][r0 * QA_STR + c0], Asrc + (size_t)r0 * 512 + c0);
    cp16(&As[0][r1 * QA_STR + c0], Asrc + (size_t)r1 * 512 + c0);
    cp16(&Bs[0][r0 * QB_STR + c0], Bsrc + (size_t)r0 * 512 + c0);
    cp16(&Bs[0][r1 * QB_STR + c0], Bsrc + (size_t)r1 * 512 + c0);
    CP_COMMIT();

    for (int it = 0; it < 32; it++) {
        if (it < 31) {
            int buf = (it + 1) & 1, kw = (it + 1) * 16;
            cp16(&As[buf][r0 * QA_STR + c0], Asrc + (size_t)r0 * 512 + kw + c0);
            cp16(&As[buf][r1 * QA_STR + c0], Asrc + (size_t)r1 * 512 + kw + c0);
            cp16(&Bs[buf][r0 * QB_STR + c0], Bsrc + (size_t)r0 * 512 + kw + c0);
            cp16(&Bs[buf][r1 * QB_STR + c0], Bsrc + (size_t)r1 * 512 + kw + c0);
            CP_COMMIT();
            asm volatile("cp.async.wait_group 1;" ::: "memory");
        } else {
            asm volatile("cp.async.wait_group 0;" ::: "memory");
        }
        __syncthreads();

        const unsigned* A = As[it & 1];
        const unsigned* B = Bs[it & 1];
#pragma unroll
        for (int step = 0; step < 2; step++) {
            const int kb = step * 8;
            uint2 a02[2], a13[2];
#pragma unroll
            for (int mt = 0; mt < 2; mt++) {
                int row = warpM + mt * 16 + g;
                a02[mt] = *(const uint2*)(A + row * QA_STR + kb + 2 * tig);
                a13[mt] = *(const uint2*)(A + (row + 8) * QA_STR + kb + 2 * tig);
            }
            uint2 bb[8];
#pragma unroll
            for (int nt = 0; nt < 8; nt++)
                bb[nt] = *(const uint2*)(B + (warpN + nt * 8 + g) * QB_STR + kb + 2 * tig);
#pragma unroll
            for (int mt = 0; mt < 2; mt++)
#pragma unroll
                for (int nt = 0; nt < 8; nt++)
                    mma16(acc[mt][nt][0], acc[mt][nt][1], acc[mt][nt][2], acc[mt][nt][3],
                          a02[mt].x, a13[mt].x, a02[mt].y, a13[mt].y, bb[nt].x, bb[nt].y);
        }
        __syncthreads();
    }

    // epilogue: +bias, pack fp16 pairs, scatter to [B,H,S][dh-words]
    unsigned* dst = (mat == 0) ? g_qh : ((mat == 1) ? g_kh : g_vh);
    const bool doperm = (mat != 2);   // V stays plain row-major for ldmatrix.trans
#pragma unroll
    for (int mt = 0; mt < 2; mt++) {
        int rr0 = m0 + warpM + mt * 16 + g;
        int rr1 = rr0 + 8;
        int bb_ = rr0 >> 11;
        int s0 = rr0 & 2047, s1 = rr1 & 2047;
#pragma unroll
        for (int nt = 0; nt < 8; nt++) {
            int col = n0 + warpN + nt * 8 + tig * 2;
            float bv0 = bias[col], bv1 = bias[col + 1];
            int w = (col & 63) >> 1;
            int pos = doperm ? ((w & ~7) | permc(w & 7)) : w;
            int hh = col >> 6;
            size_t base = (size_t)(bb_ * NHEADS + hh) * SEQ;
            dst[(base + s0) * 32 + pos] = packh2(acc[mt][nt][0] + bv0, acc[mt][nt][1] + bv1);
            dst[(base + s1) * 32 + pos] = packh2(acc[mt][nt][2] + bv0, acc[mt][nt][3] + bv1);
        }
    }
}

// ---------------------------------------------------------------------------
// Kernel 2: causal flash attention, fp16 m16n8k16 (unchanged from R11)
//   grid (32, 16, 2), block 128 (4 warps), cp.async double-buffered K/V,
//   P in registers, V via ldmatrix.x4.trans.
// ---------------------------------------------------------------------------
#define KSTRD 40
#define VSTRD 36
#define KBUF  (64 * KSTRD)
#define VBUF  (64 * VSTRD)
#define ATT_SMEM_WORDS (64 * KSTRD + 2 * KBUF + 2 * VBUF)
#define ATT_SMEM_BYTES (ATT_SMEM_WORDS * 4)

__global__ __launch_bounds__(128, 4)
void attn_kernel(float* __restrict__ out) {
    extern __shared__ unsigned smem[];
    unsigned* Qs = smem;
    unsigned* Ks = Qs + 64 * KSTRD;
    unsigned* Vs = Ks + 2 * KBUF;

    const int tid  = threadIdx.x;
    const int wid  = tid >> 5;
    const int lane = tid & 31;
    const int g    = lane >> 2;
    const int tig  = lane & 3;

    const int b  = blockIdx.z;
    const int h  = blockIdx.y;
    const int qt = (int)gridDim.x - 1 - (int)blockIdx.x;  // long tiles first
    const int q0 = qt * 64;

    const size_t hw = (size_t)(b * NHEADS + h) * SEQ * 32;
    const unsigned* gq = g_qh + hw;
    const unsigned* gk = g_kh + hw;
    const unsigned* gv = g_vh + hw;

    const int nkt = qt + 1;

#pragma unroll
    for (int i = 0; i < 4; i++) {
        int id = tid + i * 128;
        int r = id >> 3, c = (id & 7) * 4;
        cp16(Ks + r * KSTRD + c, gk + (size_t)r * 32 + c);
        cp16(Vs + r * VSTRD + c, gv + (size_t)r * 32 + c);
    }
    CP_COMMIT();

#pragma unroll
    for (int i = 0; i < 4; i++) {
        int id = tid + i * 128;
        int r = id >> 3, c = (id & 7) * 4;
        *(uint4*)(Qs + r * KSTRD + c) = *(const uint4*)(gq + (size_t)(q0 + r) * 32 + c);
    }

    float Oa[8][4];
#pragma unroll
    for (int nt = 0; nt < 8; nt++)
#pragma unroll
        for (int j = 0; j < 4; j++) Oa[nt][j] = 0.f;

    float mrow0 = -1e30f, mrow1 = -1e30f, lrow0 = 0.f, lrow1 = 0.f;
    const int rowbase = wid * 16;
    const int qrow0 = q0 + rowbase + g;
    const int qrow1 = qrow0 + 8;

    const int vlb = (lane & 15) * VSTRD + ((lane >> 4) << 2);

    for (int kt = 0; kt < nkt; kt++) {
        const unsigned* K = Ks + (kt & 1) * KBUF;
        const unsigned* V = Vs + (kt & 1) * VBUF;
        if (kt + 1 < nkt) {
            const int nb = (kt + 1) & 1;
            const size_t kb0 = (size_t)(kt + 1) * 64;
#pragma unroll
            for (int i = 0; i < 4; i++) {
                int id = tid + i * 128;
                int r = id >> 3, c = (id & 7) * 4;
                cp16(Ks + nb * KBUF + r * KSTRD + c, gk + (kb0 + r) * 32 + c);
                cp16(Vs + nb * VBUF + r * VSTRD + c, gv + (kb0 + r) * 32 + c);
            }
            CP_COMMIT();
            asm volatile("cp.async.wait_group 1;" ::: "memory");
        } else {
            asm volatile("cp.async.wait_group 0;" ::: "memory");
        }
        __syncthreads();

        const int kbase = kt * 64;

        float sacc[8][4];
#pragma unroll
        for (int nt = 0; nt < 8; nt++) {
            sacc[nt][0] = 0.f; sacc[nt][1] = 0.f; sacc[nt][2] = 0.f; sacc[nt][3] = 0.f;
        }
#pragma unroll
        for (int s = 0; s < 4; s++) {
            const int kb = s * 8;
            uint2 a02 = *(const uint2*)(Qs + (rowbase + g) * KSTRD + kb + 2 * tig);
            uint2 a13 = *(const uint2*)(Qs + (rowbase + 8 + g) * KSTRD + kb + 2 * tig);
#pragma unroll
            for (int nt = 0; nt < 8; nt++) {
                uint2 bb = *(const uint2*)(K + (nt * 8 + g) * KSTRD + kb + 2 * tig);
                mma16(sacc[nt][0], sacc[nt][1], sacc[nt][2], sacc[nt][3],
                      a02.x, a13.x, a02.y, a13.y, bb.x, bb.y);
            }
        }

        float rmax0 = -1e30f, rmax1 = -1e30f;
#pragma unroll
        for (int nt = 0; nt < 8; nt++) {
            int c0 = kbase + nt * 8 + tig * 2;
            float v0 = sacc[nt][0] * 0.125f + ((c0     > qrow0) ? -1.25e8f : 0.f);
            float v1 = sacc[nt][1] * 0.125f + ((c0 + 1 > qrow0) ? -1.25e8f : 0.f);
            float v2 = sacc[nt][2] * 0.125f + ((c0     > qrow1) ? -1.25e8f : 0.f);
            float v3 = sacc[nt][3] * 0.125f + ((c0 + 1 > qrow1) ? -1.25e8f : 0.f);
            sacc[nt][0] = v0; sacc[nt][1] = v1; sacc[nt][2] = v2; sacc[nt][3] = v3;
            rmax0 = fmaxf(rmax0, fmaxf(v0, v1));
            rmax1 = fmaxf(rmax1, fmaxf(v2, v3));
        }
        rmax0 = fmaxf(rmax0, __shfl_xor_sync(0xffffffffu, rmax0, 1));
        rmax0 = fmaxf(rmax0, __shfl_xor_sync(0xffffffffu, rmax0, 2));
        rmax1 = fmaxf(rmax1, __shfl_xor_sync(0xffffffffu, rmax1, 1));
        rmax1 = fmaxf(rmax1, __shfl_xor_sync(0xffffffffu, rmax1, 2));

        float mnew0 = fmaxf(mrow0, rmax0);
        float mnew1 = fmaxf(mrow1, rmax1);
        float alpha0 = __expf(mrow0 - mnew0);
        float alpha1 = __expf(mrow1 - mnew1);

        float rs0 = 0.f, rs1 = 0.f;
#pragma unroll
        for (int nt = 0; nt < 8; nt++) {
            float p0 = __expf(sacc[nt][0] - mnew0);
            float p1 = __expf(sacc[nt][1] - mnew0);
            float p2 = __expf(sacc[nt][2] - mnew1);
            float p3 = __expf(sacc[nt][3] - mnew1);
            rs0 += p0 + p1;
            rs1 += p2 + p3;
            sacc[nt][0] = p0; sacc[nt][1] = p1; sacc[nt][2] = p2; sacc[nt][3] = p3;
            Oa[nt][0] *= alpha0; Oa[nt][1] *= alpha0;
            Oa[nt][2] *= alpha1; Oa[nt][3] *= alpha1;
        }
        rs0 += __shfl_xor_sync(0xffffffffu, rs0, 1);
        rs0 += __shfl_xor_sync(0xffffffffu, rs0, 2);
        rs1 += __shfl_xor_sync(0xffffffffu, rs1, 1);
        rs1 += __shfl_xor_sync(0xffffffffu, rs1, 2);
        lrow0 = lrow0 * alpha0 + rs0;
        lrow1 = lrow1 * alpha1 + rs1;
        mrow0 = mnew0; mrow1 = mnew1;

#pragma unroll
        for (int s = 0; s < 4; s++) {
            unsigned a0 = packh2(sacc[2 * s][0],     sacc[2 * s][1]);
            unsigned a1 = packh2(sacc[2 * s][2],     sacc[2 * s][3]);
            unsigned a2 = packh2(sacc[2 * s + 1][0], sacc[2 * s + 1][1]);
            unsigned a3 = packh2(sacc[2 * s + 1][2], sacc[2 * s + 1][3]);
            const unsigned* vrow = V + s * 16 * VSTRD + vlb;
#pragma unroll
            for (int ntp = 0; ntp < 4; ntp++) {
                unsigned b0, b1, b2, b3;
                ldmT4(b0, b1, b2, b3, vrow + ntp * 8);
                mma16(Oa[2 * ntp][0],     Oa[2 * ntp][1],     Oa[2 * ntp][2],     Oa[2 * ntp][3],
                      a0, a1, a2, a3, b0, b1);
                mma16(Oa[2 * ntp + 1][0], Oa[2 * ntp + 1][1], Oa[2 * ntp + 1][2], Oa[2 * ntp + 1][3],
                      a0, a1, a2, a3, b2, b3);
            }
        }
        __syncthreads();
    }

    float inv0 = 1.f / lrow0;
    float inv1 = 1.f / lrow1;
    float* o0 = out + ((size_t)(b * SEQ + qrow0)) * DMODEL + h * HDIM;
    float* o1 = out + ((size_t)(b * SEQ + qrow1)) * DMODEL + h * HDIM;
#pragma unroll
    for (int nt = 0; nt < 8; nt++) {
        int dh = nt * 8 + tig * 2;
        *(float2*)(o0 + dh) = make_float2(Oa[nt][0] * inv0, Oa[nt][1] * inv0);
        *(float2*)(o1 + dh) = make_float2(Oa[nt][2] * inv1, Oa[nt][3] * inv1);
    }
}

// ---------------------------------------------------------------------------
// Launch
// ---------------------------------------------------------------------------
extern "C" void kernel_launch(void* const* d_in, const int* in_sizes, int n_in,
                              void* d_out, int out_size) {
    (void)in_sizes; (void)n_in; (void)out_size;
    const float* x  = (const float*)d_in[0];
    const float* Wq = (const float*)d_in[1];
    const float* bq = (const float*)d_in[2];
    const float* Wk = (const float*)d_in[3];
    const float* bk = (const float*)d_in[4];
    const float* Wv = (const float*)d_in[5];
    const float* bv = (const float*)d_in[6];
    float* out = (float*)d_out;

    pack_x_kernel<<<1024, 256>>>(x);
    pack_w_kernel<<<768, 256>>>(Wq, Wk, Wv);

    dim3 gq(24, 32, 1);
    qkv_h<<<gq, 256>>>(bq, bk, bv);

    cudaFuncSetAttribute(attn_kernel, cudaFuncAttributeMaxDynamicSharedMemorySize,
                         ATT_SMEM_BYTES);
    dim3 ga(32, 16, 2);
    attn_kernel<<<ga, 128, ATT_SMEM_BYTES>>>(out);
}

// round 15
// speedup vs baseline: 1.0418x; 1.0418x over previous
#include <cuda_runtime.h>
#include <cuda_fp16.h>
#include <cstdint>

// ---------------------------------------------------------------------------
//   x [2,2048,1024] f32, Wq/Wk/Wv [1024,1024] f32 ([k][n]), bq/bk/bv [1024]
//   out [2,2048,1024] f32 = causal MHA, 16 heads, head_dim 64,
//   softmax((QK^T + mask)/8)
// fp16 datapath; legacy mma.m16n8k16 (harness compiles compute_103, no 'a').
// ---------------------------------------------------------------------------

#define NHEADS 16
#define HDIM   64
#define SEQ    2048
#define BATCH  2
#define DMODEL 1024

__device__ unsigned g_xh[4096 * 512];            // x  [m][k-words], permuted groups
__device__ unsigned g_wt[3 * 1024 * 512];        // W^T [mat][n][k-words], permuted
__device__ unsigned g_qh[BATCH * NHEADS * SEQ * 32];  // [b,h,s][dh-words], permuted
__device__ unsigned g_kh[BATCH * NHEADS * SEQ * 32];  // permuted
__device__ unsigned g_vh[BATCH * NHEADS * SEQ * 32];  // plain (ldmatrix.trans)

// ---------------------------------------------------------------------------
// helpers — mma.m16n8k16 fp16, thread (g=lane>>2, tig=lane&3):
//   A row: a0=(g,2tig..+1) a1=(g+8,2tig..) a2=(g,2tig+8..) a3=(g+8,2tig+8..)
//   B col: b0=(k 2tig..+1, n g) b1=(k 2tig+8.., n g)
//   C:     c0=(g,2tig) c1=(g,2tig+1) c2=(g+8,2tig) c3=(g+8,2tig+1)
//   => QK C-frag == PV A-frag layout; P never touches smem.
//   Word perm within 8-word group: [0,4,1,5,2,6,3,7] -> (tig,tig+4) adjacent.
// ---------------------------------------------------------------------------
__device__ __forceinline__ int permc(int w) { return ((w & 3) << 1) | (w >> 2); }

__device__ __forceinline__ unsigned packh2(float lo, float hi) {
    __half2 h = __floats2half2_rn(lo, hi);
    return *(unsigned*)&h;
}

__device__ __forceinline__ float ex2f(float x) {
    float r; asm("ex2.approx.f32 %0, %1;" : "=f"(r) : "f"(x)); return r;
}
__device__ __forceinline__ unsigned h2ex2(unsigned x) {
    unsigned r; asm("ex2.approx.f16x2 %0, %1;" : "=r"(r) : "r"(x)); return r;
}

__device__ __forceinline__ void mma16(float& d0, float& d1, float& d2, float& d3,
                                      unsigned a0, unsigned a1, unsigned a2, unsigned a3,
                                      unsigned b0, unsigned b1) {
    asm("mma.sync.aligned.m16n8k16.row.col.f32.f16.f16.f32 "
        "{%0,%1,%2,%3},{%4,%5,%6,%7},{%8,%9},{%0,%1,%2,%3};"
        : "+f"(d0), "+f"(d1), "+f"(d2), "+f"(d3)
        : "r"(a0), "r"(a1), "r"(a2), "r"(a3), "r"(b0), "r"(b1));
}

__device__ __forceinline__ void ldmT4(unsigned& r0, unsigned& r1,
                                      unsigned& r2, unsigned& r3, const void* p) {
    unsigned a = (unsigned)__cvta_generic_to_shared(p);
    asm volatile("ldmatrix.sync.aligned.m8n8.x4.trans.shared.b16 {%0,%1,%2,%3}, [%4];"
                 : "=r"(r0), "=r"(r1), "=r"(r2), "=r"(r3) : "r"(a));
}

__device__ __forceinline__ void cp16(void* smem, const void* gmem) {
    unsigned s = (unsigned)__cvta_generic_to_shared(smem);
    asm volatile("cp.async.ca.shared.global [%0], [%1], 16;" :: "r"(s), "l"(gmem));
}
#define CP_COMMIT() asm volatile("cp.async.commit_group;" ::: "memory")

// ---------------------------------------------------------------------------
// Pre-pass (single launch): pack x and W^T -> fp16 pair-words, permuted
// ---------------------------------------------------------------------------
__global__ void pack_all(const float* __restrict__ x,
                         const float* __restrict__ Wq,
                         const float* __restrict__ Wk,
                         const float* __restrict__ Wv) {
    if (blockIdx.x < 1024) {
        int idx = blockIdx.x * 256 + threadIdx.x;   // 262144 groups of 16 floats
        const float4* src = (const float4*)x + (size_t)idx * 4;
        float4 f0 = src[0], f1 = src[1], f2 = src[2], f3 = src[3];
        unsigned w0 = packh2(f0.x, f0.y), w1 = packh2(f0.z, f0.w);
        unsigned w2 = packh2(f1.x, f1.y), w3 = packh2(f1.z, f1.w);
        unsigned w4 = packh2(f2.x, f2.y), w5 = packh2(f2.z, f2.w);
        unsigned w6 = packh2(f3.x, f3.y), w7 = packh2(f3.z, f3.w);
        uint4* dst = (uint4*)(g_xh + (size_t)idx * 8);
        dst[0] = make_uint4(w0, w4, w1, w5);   // permuted [0,4,1,5,2,6,3,7]
        dst[1] = make_uint4(w2, w6, w3, w7);
    } else {
        int id  = (blockIdx.x - 1024) * 256 + threadIdx.x;  // 196608
        int mat = id >> 16;
        int rem = id & 65535;
        int grp = rem >> 10;
        int n   = rem & 1023;
        const float* W = (mat == 0) ? Wq : ((mat == 1) ? Wk : Wv);
        int k0 = grp * 16;
        float f[16];
#pragma unroll
        for (int j = 0; j < 16; j++) f[j] = W[(size_t)(k0 + j) * DMODEL + n];
        unsigned w[8];
#pragma unroll
        for (int j = 0; j < 8; j++) w[j] = packh2(f[2 * j], f[2 * j + 1]);
        uint4* dst = (uint4*)(g_wt + ((size_t)mat << 19) + (size_t)n * 512 + grp * 8);
        dst[0] = make_uint4(w[0], w[4], w[1], w[5]);
        dst[1] = make_uint4(w[2], w[6], w[3], w[7]);
    }
}

// ---------------------------------------------------------------------------
// Kernel 1: QKV projection, fp16 m16n8k16, 3-stage cp.async pipeline
//   grid (24, 32): x = mat*8 + ntile (BN=128), y = m-tile (BM=128), BK=32
//   8 warps 4(M)x2(N), warp tile 32x64; one __syncthreads per k-iteration
// ---------------------------------------------------------------------------
#define QS 24
#define QKV_BUFW (128 * QS)
#define QKV_SMEM_BYTES (6 * QKV_BUFW * 4)   // 3 x (A+B) = 72 KB

__global__ __launch_bounds__(256, 2)
void qkv_h(const float* __restrict__ bq, const float* __restrict__ bk,
           const float* __restrict__ bv) {
    extern __shared__ unsigned qsm[];
    unsigned* As = qsm;                  // [3][128*QS]
    unsigned* Bs = qsm + 3 * QKV_BUFW;   // [3][128*QS]

    const int tid  = threadIdx.x;
    const int wid  = tid >> 5;
    const int lane = tid & 31;
    const int g    = lane >> 2;
    const int tig  = lane & 3;

    const int mat = blockIdx.x >> 3;
    const int n0  = (blockIdx.x & 7) * 128;
    const int m0  = blockIdx.y * 128;

    const unsigned* Asrc = g_xh + (size_t)m0 * 512;
    const unsigned* Bsrc = g_wt + ((size_t)mat << 19) + (size_t)n0 * 512;
    const float* bias = (mat == 0) ? bq : ((mat == 1) ? bk : bv);

    const int warpM = (wid & 3) * 32;
    const int warpN = (wid >> 2) * 64;

    float acc[2][8][4];
#pragma unroll
    for (int mt = 0; mt < 2; mt++)
#pragma unroll
        for (int nt = 0; nt < 8; nt++)
#pragma unroll
            for (int j = 0; j < 4; j++) acc[mt][nt][j] = 0.f;

    const int r0 = tid >> 2, c0 = (tid & 3) * 4;
    const int r1 = r0 + 64;

#define QKV_STAGE(buf, kw)                                                     \
    do {                                                                       \
        unsigned* A_ = As + (buf) * QKV_BUFW;                                  \
        unsigned* B_ = Bs + (buf) * QKV_BUFW;                                  \
        cp16(&A_[r0 * QS + c0], Asrc + (size_t)r0 * 512 + (kw) + c0);          \
        cp16(&A_[r1 * QS + c0], Asrc + (size_t)r1 * 512 + (kw) + c0);          \
        cp16(&B_[r0 * QS + c0], Bsrc + (size_t)r0 * 512 + (kw) + c0);          \
        cp16(&B_[r1 * QS + c0], Bsrc + (size_t)r1 * 512 + (kw) + c0);          \
    } while (0)

    QKV_STAGE(0, 0);  CP_COMMIT();
    QKV_STAGE(1, 16); CP_COMMIT();

    for (int it = 0; it < 32; it++) {
        asm volatile("cp.async.wait_group 1;" ::: "memory");
        __syncthreads();

        const unsigned* A = As + (it % 3) * QKV_BUFW;
        const unsigned* B = Bs + (it % 3) * QKV_BUFW;
#pragma unroll
        for (int step = 0; step < 2; step++) {
            const int kb = step * 8;
            uint2 a02[2], a13[2];
#pragma unroll
            for (int mt = 0; mt < 2; mt++) {
                int row = warpM + mt * 16 + g;
                a02[mt] = *(const uint2*)(A + row * QS + kb + 2 * tig);
                a13[mt] = *(const uint2*)(A + (row + 8) * QS + kb + 2 * tig);
            }
            uint2 bb[8];
#pragma unroll
            for (int nt = 0; nt < 8; nt++)
                bb[nt] = *(const uint2*)(B + (warpN + nt * 8 + g) * QS + kb + 2 * tig);
#pragma unroll
            for (int mt = 0; mt < 2; mt++)
#pragma unroll
                for (int nt = 0; nt < 8; nt++)
                    mma16(acc[mt][nt][0], acc[mt][nt][1], acc[mt][nt][2], acc[mt][nt][3],
                          a02[mt].x, a13[mt].x, a02[mt].y, a13[mt].y, bb[nt].x, bb[nt].y);
        }
        if (it + 2 < 32) QKV_STAGE((it + 2) % 3, (it + 2) * 16);
        CP_COMMIT();
    }

    // epilogue: +bias, pack fp16 pairs, scatter to [B,H,S][dh-words]
    unsigned* dst = (mat == 0) ? g_qh : ((mat == 1) ? g_kh : g_vh);
    const bool doperm = (mat != 2);
#pragma unroll
    for (int mt = 0; mt < 2; mt++) {
        int rr0 = m0 + warpM + mt * 16 + g;
        int rr1 = rr0 + 8;
        int bb_ = rr0 >> 11;
        int s0 = rr0 & 2047, s1 = rr1 & 2047;
#pragma unroll
        for (int nt = 0; nt < 8; nt++) {
            int col = n0 + warpN + nt * 8 + tig * 2;
            float bv0 = bias[col], bv1 = bias[col + 1];
            int w = (col & 63) >> 1;
            int pos = doperm ? ((w & ~7) | permc(w & 7)) : w;
            int hh = col >> 6;
            size_t base = (size_t)(bb_ * NHEADS + hh) * SEQ;
            dst[(base + s0) * 32 + pos] = packh2(acc[mt][nt][0] + bv0, acc[mt][nt][1] + bv1);
            dst[(base + s1) * 32 + pos] = packh2(acc[mt][nt][2] + bv0, acc[mt][nt][3] + bv1);
        }
    }
}

// ---------------------------------------------------------------------------
// Kernel 2: causal flash attention, fp16 m16n8k16
//   grid (32, 16, 2), block 128 (4 warps), cp.async double-buffered K/V.
//   P in registers; softmax in log2 domain via ex2.approx.f16x2;
//   row-sums via ones-column MMA (exact f32, no shuffles);
//   causal mask applied only on the diagonal k-tile.
// ---------------------------------------------------------------------------
#define KSTRD 40
#define VSTRD 36
#define KBUF  (64 * KSTRD)
#define VBUF  (64 * VSTRD)
#define ATT_SMEM_WORDS (64 * KSTRD + 2 * KBUF + 2 * VBUF)
#define ATT_SMEM_BYTES (ATT_SMEM_WORDS * 4)
#define H2ONES 0x3C003C00u

__global__ __launch_bounds__(128, 4)
void attn_kernel(float* __restrict__ out) {
    extern __shared__ unsigned smem[];
    unsigned* Qs = smem;
    unsigned* Ks = Qs + 64 * KSTRD;
    unsigned* Vs = Ks + 2 * KBUF;

    const int tid  = threadIdx.x;
    const int wid  = tid >> 5;
    const int lane = tid & 31;
    const int g    = lane >> 2;
    const int tig  = lane & 3;

    const int b  = blockIdx.z;
    const int h  = blockIdx.y;
    const int qt = (int)gridDim.x - 1 - (int)blockIdx.x;  // long tiles first
    const int q0 = qt * 64;

    const size_t hw = (size_t)(b * NHEADS + h) * SEQ * 32;
    const unsigned* gq = g_qh + hw;
    const unsigned* gk = g_kh + hw;
    const unsigned* gv = g_vh + hw;

    const int nkt = qt + 1;

#pragma unroll
    for (int i = 0; i < 4; i++) {
        int id = tid + i * 128;
        int r = id >> 3, c = (id & 7) * 4;
        cp16(Ks + r * KSTRD + c, gk + (size_t)r * 32 + c);
        cp16(Vs + r * VSTRD + c, gv + (size_t)r * 32 + c);
    }
    CP_COMMIT();

#pragma unroll
    for (int i = 0; i < 4; i++) {
        int id = tid + i * 128;
        int r = id >> 3, c = (id & 7) * 4;
        *(uint4*)(Qs + r * KSTRD + c) = *(const uint4*)(gq + (size_t)(q0 + r) * 32 + c);
    }

    float Oa[8][4];
#pragma unroll
    for (int nt = 0; nt < 8; nt++)
#pragma unroll
        for (int j = 0; j < 4; j++) Oa[nt][j] = 0.f;

    // running state in the log2 domain: m = max of w, l = sum of 2^(w-m)
    float mrow0 = -1e30f, mrow1 = -1e30f, lrow0 = 0.f, lrow1 = 0.f;
    const int rowbase = wid * 16;
    const int qrow0 = q0 + rowbase + g;
    const int qrow1 = qrow0 + 8;
    const float SCL = 0.18033688011112042f;  // 0.125 * log2(e)

    const int vlb = (lane & 15) * VSTRD + ((lane >> 4) << 2);

    for (int kt = 0; kt < nkt; kt++) {
        const unsigned* K = Ks + (kt & 1) * KBUF;
        const unsigned* V = Vs + (kt & 1) * VBUF;
        if (kt + 1 < nkt) {
            const int nb = (kt + 1) & 1;
            const size_t kb0 = (size_t)(kt + 1) * 64;
#pragma unroll
            for (int i = 0; i < 4; i++) {
                int id = tid + i * 128;
                int r = id >> 3, c = (id & 7) * 4;
                cp16(Ks + nb * KBUF + r * KSTRD + c, gk + (kb0 + r) * 32 + c);
                cp16(Vs + nb * VBUF + r * VSTRD + c, gv + (kb0 + r) * 32 + c);
            }
            CP_COMMIT();
            asm volatile("cp.async.wait_group 1;" ::: "memory");
        } else {
            asm volatile("cp.async.wait_group 0;" ::: "memory");
        }
        __syncthreads();

        // S = Q K^T (Dh=64 -> 4 k16 steps)
        float sacc[8][4];
#pragma unroll
        for (int nt = 0; nt < 8; nt++) {
            sacc[nt][0] = 0.f; sacc[nt][1] = 0.f; sacc[nt][2] = 0.f; sacc[nt][3] = 0.f;
        }
#pragma unroll
        for (int s = 0; s < 4; s++) {
            const int kb = s * 8;
            uint2 a02 = *(const uint2*)(Qs + (rowbase + g) * KSTRD + kb + 2 * tig);
            uint2 a13 = *(const uint2*)(Qs + (rowbase + 8 + g) * KSTRD + kb + 2 * tig);
#pragma unroll
            for (int nt = 0; nt < 8; nt++) {
                uint2 bb = *(const uint2*)(K + (nt * 8 + g) * KSTRD + kb + 2 * tig);
                mma16(sacc[nt][0], sacc[nt][1], sacc[nt][2], sacc[nt][3],
                      a02.x, a13.x, a02.y, a13.y, bb.x, bb.y);
            }
        }

        // w = S*0.125*log2e (+ mask on the diagonal tile only); track row max
        float rmax0 = -1e30f, rmax1 = -1e30f;
        if (kt == nkt - 1) {
            const int kbase = kt * 64;
#pragma unroll
            for (int nt = 0; nt < 8; nt++) {
                int c0 = kbase + nt * 8 + tig * 2;
                float v0 = sacc[nt][0] * SCL + ((c0     > qrow0) ? -6e8f : 0.f);
                float v1 = sacc[nt][1] * SCL + ((c0 + 1 > qrow0) ? -6e8f : 0.f);
                float v2 = sacc[nt][2] * SCL + ((c0     > qrow1) ? -6e8f : 0.f);
                float v3 = sacc[nt][3] * SCL + ((c0 + 1 > qrow1) ? -6e8f : 0.f);
                sacc[nt][0] = v0; sacc[nt][1] = v1; sacc[nt][2] = v2; sacc[nt][3] = v3;
                rmax0 = fmaxf(rmax0, fmaxf(v0, v1));
                rmax1 = fmaxf(rmax1, fmaxf(v2, v3));
            }
        } else {
#pragma unroll
            for (int nt = 0; nt < 8; nt++) {
                float v0 = sacc[nt][0] * SCL;
                float v1 = sacc[nt][1] * SCL;
                float v2 = sacc[nt][2] * SCL;
                float v3 = sacc[nt][3] * SCL;
                sacc[nt][0] = v0; sacc[nt][1] = v1; sacc[nt][2] = v2; sacc[nt][3] = v3;
                rmax0 = fmaxf(rmax0, fmaxf(v0, v1));
                rmax1 = fmaxf(rmax1, fmaxf(v2, v3));
            }
        }
        rmax0 = fmaxf(rmax0, __shfl_xor_sync(0xffffffffu, rmax0, 1));
        rmax0 = fmaxf(rmax0, __shfl_xor_sync(0xffffffffu, rmax0, 2));
        rmax1 = fmaxf(rmax1, __shfl_xor_sync(0xffffffffu, rmax1, 1));
        rmax1 = fmaxf(rmax1, __shfl_xor_sync(0xffffffffu, rmax1, 2));

        float mnew0 = fmaxf(mrow0, rmax0);
        float mnew1 = fmaxf(mrow1, rmax1);
        float alpha0 = ex2f(mrow0 - mnew0);
        float alpha1 = ex2f(mrow1 - mnew1);
        mrow0 = mnew0; mrow1 = mnew1;

        // P = 2^(w - mnew) straight into packed fp16 (PV A-fragment layout)
        unsigned plo[8], phi[8];
#pragma unroll
        for (int nt = 0; nt < 8; nt++) {
            plo[nt] = h2ex2(packh2(sacc[nt][0] - mnew0, sacc[nt][1] - mnew0));
            phi[nt] = h2ex2(packh2(sacc[nt][2] - mnew1, sacc[nt][3] - mnew1));
        }

        // row sums via ones-column MMA (exact f32 sum of the SAME fp16 P)
        float rs0 = 0.f, rsx = 0.f, rs1 = 0.f, rsy = 0.f;
#pragma unroll
        for (int s = 0; s < 4; s++)
            mma16(rs0, rsx, rs1, rsy,
                  plo[2 * s], phi[2 * s], plo[2 * s + 1], phi[2 * s + 1],
                  H2ONES, H2ONES);
        lrow0 = lrow0 * alpha0 + rs0;
        lrow1 = lrow1 * alpha1 + rs1;

#pragma unroll
        for (int nt = 0; nt < 8; nt++) {
            Oa[nt][0] *= alpha0; Oa[nt][1] *= alpha0;
            Oa[nt][2] *= alpha1; Oa[nt][3] *= alpha1;
        }

        // O += P V
#pragma unroll
        for (int s = 0; s < 4; s++) {
            unsigned a0 = plo[2 * s], a1 = phi[2 * s];
            unsigned a2 = plo[2 * s + 1], a3 = phi[2 * s + 1];
            const unsigned* vrow = V + s * 16 * VSTRD + vlb;
#pragma unroll
            for (int ntp = 0; ntp < 4; ntp++) {
                unsigned b0, b1, b2, b3;
                ldmT4(b0, b1, b2, b3, vrow + ntp * 8);
                mma16(Oa[2 * ntp][0],     Oa[2 * ntp][1],     Oa[2 * ntp][2],     Oa[2 * ntp][3],
                      a0, a1, a2, a3, b0, b1);
                mma16(Oa[2 * ntp + 1][0], Oa[2 * ntp + 1][1], Oa[2 * ntp + 1][2], Oa[2 * ntp + 1][3],
                      a0, a1, a2, a3, b2, b3);
            }
        }
        __syncthreads();
    }

    float inv0 = 1.f / lrow0;
    float inv1 = 1.f / lrow1;
    float* o0 = out + ((size_t)(b * SEQ + qrow0)) * DMODEL + h * HDIM;
    float* o1 = out + ((size_t)(b * SEQ + qrow1)) * DMODEL + h * HDIM;
#pragma unroll
    for (int nt = 0; nt < 8; nt++) {
        int dh = nt * 8 + tig * 2;
        *(float2*)(o0 + dh) = make_float2(Oa[nt][0] * inv0, Oa[nt][1] * inv0);
        *(float2*)(o1 + dh) = make_float2(Oa[nt][2] * inv1, Oa[nt][3] * inv1);
    }
}

// ---------------------------------------------------------------------------
// Launch
// ---------------------------------------------------------------------------
extern "C" void kernel_launch(void* const* d_in, const int* in_sizes, int n_in,
                              void* d_out, int out_size) {
    (void)in_sizes; (void)n_in; (void)out_size;
    const float* x  = (const float*)d_in[0];
    const float* Wq = (const float*)d_in[1];
    const float* bq = (const float*)d_in[2];
    const float* Wk = (const float*)d_in[3];
    const float* bk = (const float*)d_in[4];
    const float* Wv = (const float*)d_in[5];
    const float* bv = (const float*)d_in[6];
    float* out = (float*)d_out;

    pack_all<<<1792, 256>>>(x, Wq, Wk, Wv);

    cudaFuncSetAttribute(qkv_h, cudaFuncAttributeMaxDynamicSharedMemorySize,
                         QKV_SMEM_BYTES);
    dim3 gq(24, 32, 1);
    qkv_h<<<gq, 256, QKV_SMEM_BYTES>>>(bq, bk, bv);

    cudaFuncSetAttribute(attn_kernel, cudaFuncAttributeMaxDynamicSharedMemorySize,
                         ATT_SMEM_BYTES);
    dim3 ga(32, 16, 2);
    attn_kernel<<<ga, 128, ATT_SMEM_BYTES>>>(out);
}

// round 16
// speedup vs baseline: 1.0830x; 1.0395x over previous
#include <cuda_runtime.h>
#include <cuda_fp16.h>
#include <cstdint>

// ---------------------------------------------------------------------------
//   x [2,2048,1024] f32, Wq/Wk/Wv [1024,1024] f32 ([k][n]), bq/bk/bv [1024]
//   out [2,2048,1024] f32 = causal MHA, 16 heads, head_dim 64,
//   softmax((QK^T + mask)/8)
// fp16 datapath; legacy mma.m16n8k16 (harness compiles compute_103, no 'a').
// Q is pre-scaled by 0.125*log2(e) so QK^T lands directly in the log2 domain.
// ---------------------------------------------------------------------------

#define NHEADS 16
#define HDIM   64
#define SEQ    2048
#define BATCH  2
#define DMODEL 1024

__device__ unsigned g_xh[4096 * 512];            // x  [m][k-words], permuted groups
__device__ unsigned g_wt[3 * 1024 * 512];        // W^T [mat][n][k-words], permuted
__device__ unsigned g_qh[BATCH * NHEADS * SEQ * 32];  // [b,h,s][dh-words], plain, pre-scaled
__device__ unsigned g_kh[BATCH * NHEADS * SEQ * 32];  // plain
__device__ unsigned g_vh[BATCH * NHEADS * SEQ * 32];  // plain

// ---------------------------------------------------------------------------
// helpers
// ---------------------------------------------------------------------------
__device__ __forceinline__ int permc(int w) { return ((w & 3) << 1) | (w >> 2); }

__device__ __forceinline__ unsigned packh2(float lo, float hi) {
    __half2 h = __floats2half2_rn(lo, hi);
    return *(unsigned*)&h;
}

__device__ __forceinline__ float ex2f(float x) {
    float r; asm("ex2.approx.f32 %0, %1;" : "=f"(r) : "f"(x)); return r;
}
__device__ __forceinline__ unsigned h2ex2(unsigned x) {
    unsigned r; asm("ex2.approx.f16x2 %0, %1;" : "=r"(r) : "r"(x)); return r;
}

__device__ __forceinline__ void mma16(float& d0, float& d1, float& d2, float& d3,
                                      unsigned a0, unsigned a1, unsigned a2, unsigned a3,
                                      unsigned b0, unsigned b1) {
    asm("mma.sync.aligned.m16n8k16.row.col.f32.f16.f16.f32 "
        "{%0,%1,%2,%3},{%4,%5,%6,%7},{%8,%9},{%0,%1,%2,%3};"
        : "+f"(d0), "+f"(d1), "+f"(d2), "+f"(d3)
        : "r"(a0), "r"(a1), "r"(a2), "r"(a3), "r"(b0), "r"(b1));
}

// ldmatrix x4 (non-transposed): 8x8 b16 tiles, fragment == mma A/B layout
__device__ __forceinline__ void ldm4(unsigned& r0, unsigned& r1,
                                     unsigned& r2, unsigned& r3, const void* p) {
    unsigned a = (unsigned)__cvta_generic_to_shared(p);
    asm volatile("ldmatrix.sync.aligned.m8n8.x4.shared.b16 {%0,%1,%2,%3}, [%4];"
                 : "=r"(r0), "=r"(r1), "=r"(r2), "=r"(r3) : "r"(a));
}
// ldmatrix x4 transposed (for V)
__device__ __forceinline__ void ldmT4(unsigned& r0, unsigned& r1,
                                      unsigned& r2, unsigned& r3, const void* p) {
    unsigned a = (unsigned)__cvta_generic_to_shared(p);
    asm volatile("ldmatrix.sync.aligned.m8n8.x4.trans.shared.b16 {%0,%1,%2,%3}, [%4];"
                 : "=r"(r0), "=r"(r1), "=r"(r2), "=r"(r3) : "r"(a));
}

__device__ __forceinline__ void cp16(void* smem, const void* gmem) {
    unsigned s = (unsigned)__cvta_generic_to_shared(smem);
    asm volatile("cp.async.ca.shared.global [%0], [%1], 16;" :: "r"(s), "l"(gmem));
}
#define CP_COMMIT() asm volatile("cp.async.commit_group;" ::: "memory")

// ---------------------------------------------------------------------------
// Pre-pass (single launch): pack x and W^T -> fp16 pair-words, permuted
// ---------------------------------------------------------------------------
__global__ void pack_all(const float* __restrict__ x,
                         const float* __restrict__ Wq,
                         const float* __restrict__ Wk,
                         const float* __restrict__ Wv) {
    if (blockIdx.x < 1024) {
        int idx = blockIdx.x * 256 + threadIdx.x;
        const float4* src = (const float4*)x + (size_t)idx * 4;
        float4 f0 = src[0], f1 = src[1], f2 = src[2], f3 = src[3];
        unsigned w0 = packh2(f0.x, f0.y), w1 = packh2(f0.z, f0.w);
        unsigned w2 = packh2(f1.x, f1.y), w3 = packh2(f1.z, f1.w);
        unsigned w4 = packh2(f2.x, f2.y), w5 = packh2(f2.z, f2.w);
        unsigned w6 = packh2(f3.x, f3.y), w7 = packh2(f3.z, f3.w);
        uint4* dst = (uint4*)(g_xh + (size_t)idx * 8);
        dst[0] = make_uint4(w0, w4, w1, w5);
        dst[1] = make_uint4(w2, w6, w3, w7);
    } else {
        int id  = (blockIdx.x - 1024) * 256 + threadIdx.x;
        int mat = id >> 16;
        int rem = id & 65535;
        int grp = rem >> 10;
        int n   = rem & 1023;
        const float* W = (mat == 0) ? Wq : ((mat == 1) ? Wk : Wv);
        int k0 = grp * 16;
        float f[16];
#pragma unroll
        for (int j = 0; j < 16; j++) f[j] = W[(size_t)(k0 + j) * DMODEL + n];
        unsigned w[8];
#pragma unroll
        for (int j = 0; j < 8; j++) w[j] = packh2(f[2 * j], f[2 * j + 1]);
        uint4* dst = (uint4*)(g_wt + ((size_t)mat << 19) + (size_t)n * 512 + grp * 8);
        dst[0] = make_uint4(w[0], w[4], w[1], w[5]);
        dst[1] = make_uint4(w[2], w[6], w[3], w[7]);
    }
}

// ---------------------------------------------------------------------------
// Kernel 1: QKV projection, fp16 m16n8k16, 3-stage cp.async pipeline
//   grid (24, 32); 8 warps 4(M)x2(N), warp tile 32x64.
//   Epilogue writes plain layouts; Q (and bq) pre-scaled by 0.125*log2e.
// ---------------------------------------------------------------------------
#define QS 24
#define QKV_BUFW (128 * QS)
#define QKV_SMEM_BYTES (6 * QKV_BUFW * 4)   // 72 KB

__global__ __launch_bounds__(256, 2)
void qkv_h(const float* __restrict__ bq, const float* __restrict__ bk,
           const float* __restrict__ bv) {
    extern __shared__ unsigned qsm[];
    unsigned* As = qsm;
    unsigned* Bs = qsm + 3 * QKV_BUFW;

    const int tid  = threadIdx.x;
    const int wid  = tid >> 5;
    const int lane = tid & 31;
    const int g    = lane >> 2;
    const int tig  = lane & 3;

    const int mat = blockIdx.x >> 3;
    const int n0  = (blockIdx.x & 7) * 128;
    const int m0  = blockIdx.y * 128;

    const unsigned* Asrc = g_xh + (size_t)m0 * 512;
    const unsigned* Bsrc = g_wt + ((size_t)mat << 19) + (size_t)n0 * 512;
    const float* bias = (mat == 0) ? bq : ((mat == 1) ? bk : bv);

    const int warpM = (wid & 3) * 32;
    const int warpN = (wid >> 2) * 64;

    float acc[2][8][4];
#pragma unroll
    for (int mt = 0; mt < 2; mt++)
#pragma unroll
        for (int nt = 0; nt < 8; nt++)
#pragma unroll
            for (int j = 0; j < 4; j++) acc[mt][nt][j] = 0.f;

    const int r0 = tid >> 2, c0 = (tid & 3) * 4;
    const int r1 = r0 + 64;

#define QKV_STAGE(buf, kw)                                                     \
    do {                                                                       \
        unsigned* A_ = As + (buf) * QKV_BUFW;                                  \
        unsigned* B_ = Bs + (buf) * QKV_BUFW;                                  \
        cp16(&A_[r0 * QS + c0], Asrc + (size_t)r0 * 512 + (kw) + c0);          \
        cp16(&A_[r1 * QS + c0], Asrc + (size_t)r1 * 512 + (kw) + c0);          \
        cp16(&B_[r0 * QS + c0], Bsrc + (size_t)r0 * 512 + (kw) + c0);          \
        cp16(&B_[r1 * QS + c0], Bsrc + (size_t)r1 * 512 + (kw) + c0);          \
    } while (0)

    QKV_STAGE(0, 0);  CP_COMMIT();
    QKV_STAGE(1, 16); CP_COMMIT();

    for (int it = 0; it < 32; it++) {
        asm volatile("cp.async.wait_group 1;" ::: "memory");
        __syncthreads();

        const unsigned* A = As + (it % 3) * QKV_BUFW;
        const unsigned* B = Bs + (it % 3) * QKV_BUFW;
#pragma unroll
        for (int step = 0; step < 2; step++) {
            const int kb = step * 8;
            uint2 a02[2], a13[2];
#pragma unroll
            for (int mt = 0; mt < 2; mt++) {
                int row = warpM + mt * 16 + g;
                a02[mt] = *(const uint2*)(A + row * QS + kb + 2 * tig);
                a13[mt] = *(const uint2*)(A + (row + 8) * QS + kb + 2 * tig);
            }
            uint2 bb[8];
#pragma unroll
            for (int nt = 0; nt < 8; nt++)
                bb[nt] = *(const uint2*)(B + (warpN + nt * 8 + g) * QS + kb + 2 * tig);
#pragma unroll
            for (int mt = 0; mt < 2; mt++)
#pragma unroll
                for (int nt = 0; nt < 8; nt++)
                    mma16(acc[mt][nt][0], acc[mt][nt][1], acc[mt][nt][2], acc[mt][nt][3],
                          a02[mt].x, a13[mt].x, a02[mt].y, a13[mt].y, bb[nt].x, bb[nt].y);
        }
        if (it + 2 < 32) QKV_STAGE((it + 2) % 3, (it + 2) * 16);
        CP_COMMIT();
    }

    // epilogue: (+bias)*scale, pack fp16 pairs, plain [B,H,S][dh-words]
    unsigned* dst = (mat == 0) ? g_qh : ((mat == 1) ? g_kh : g_vh);
    const float scl = (mat == 0) ? 0.18033688011112042f : 1.0f;  // 0.125*log2e
#pragma unroll
    for (int mt = 0; mt < 2; mt++) {
        int rr0 = m0 + warpM + mt * 16 + g;
        int rr1 = rr0 + 8;
        int bb_ = rr0 >> 11;
        int s0 = rr0 & 2047, s1 = rr1 & 2047;
#pragma unroll
        for (int nt = 0; nt < 8; nt++) {
            int col = n0 + warpN + nt * 8 + tig * 2;
            float bv0 = bias[col], bv1 = bias[col + 1];
            int pos = (col & 63) >> 1;
            int hh = col >> 6;
            size_t base = (size_t)(bb_ * NHEADS + hh) * SEQ;
            dst[(base + s0) * 32 + pos] =
                packh2((acc[mt][nt][0] + bv0) * scl, (acc[mt][nt][1] + bv1) * scl);
            dst[(base + s1) * 32 + pos] =
                packh2((acc[mt][nt][2] + bv0) * scl, (acc[mt][nt][3] + bv1) * scl);
        }
    }
}

// ---------------------------------------------------------------------------
// Kernel 2: causal flash attention, fp16 m16n8k16
//   grid (32, 16, 2), block 128 (4 warps), cp.async double-buffered K/V.
//   Q/K fragments via ldmatrix.x4 (plain layout, stride 36 = conflict-free);
//   P in registers (log2-domain softmax, ex2.f16x2); row-sums via ones-MMA;
//   mask only on the diagonal tile; Oa rescale skipped when max unchanged.
// ---------------------------------------------------------------------------
#define STRD 36
#define TBUF (64 * STRD)
#define ATT_SMEM_WORDS (5 * TBUF)   // Q + 2K + 2V
#define ATT_SMEM_BYTES (ATT_SMEM_WORDS * 4)
#define H2ONES 0x3C003C00u

__global__ __launch_bounds__(128, 4)
void attn_kernel(float* __restrict__ out) {
    extern __shared__ unsigned smem[];
    unsigned* Qs = smem;
    unsigned* Ks = Qs + TBUF;
    unsigned* Vs = Ks + 2 * TBUF;

    const int tid  = threadIdx.x;
    const int wid  = tid >> 5;
    const int lane = tid & 31;
    const int tig  = lane & 3;

    const int b  = blockIdx.z;
    const int h  = blockIdx.y;
    const int qt = (int)gridDim.x - 1 - (int)blockIdx.x;  // long tiles first
    const int q0 = qt * 64;

    const size_t hw = (size_t)(b * NHEADS + h) * SEQ * 32;
    const unsigned* gq = g_qh + hw;
    const unsigned* gk = g_kh + hw;
    const unsigned* gv = g_vh + hw;

    const int nkt = qt + 1;

#pragma unroll
    for (int i = 0; i < 4; i++) {
        int id = tid + i * 128;
        int r = id >> 3, c = (id & 7) * 4;
        cp16(Ks + r * STRD + c, gk + (size_t)r * 32 + c);
        cp16(Vs + r * STRD + c, gv + (size_t)r * 32 + c);
    }
    CP_COMMIT();

#pragma unroll
    for (int i = 0; i < 4; i++) {
        int id = tid + i * 128;
        int r = id >> 3, c = (id & 7) * 4;
        *(uint4*)(Qs + r * STRD + c) = *(const uint4*)(gq + (size_t)(q0 + r) * 32 + c);
    }

    float Oa[8][4];
#pragma unroll
    for (int nt = 0; nt < 8; nt++)
#pragma unroll
        for (int j = 0; j < 4; j++) Oa[nt][j] = 0.f;

    float mrow0 = -1e30f, mrow1 = -1e30f, lrow0 = 0.f, lrow1 = 0.f;
    const int rowbase = wid * 16;
    const int qrow0 = q0 + rowbase + (lane >> 2);
    const int qrow1 = qrow0 + 8;

    // ldmatrix lane bases (stride 36 words = 144B: 8-lane phases conflict-free)
    // Q A-frag x4: m0(rows+0,k0) m1(rows+8,k0) m2(rows+0,k8) m3(rows+8,k8)
    const int qlb = ((lane & 7) + ((lane >> 3) & 1) * 8) * STRD + ((lane >> 4) & 1) * 4;
    // K B-frag x4: m0(ntp rows,k0) m1(ntp,k8) m2(ntp+8 rows,k0) m3(ntp+8,k8)
    const int klb = ((lane & 7) + ((lane >> 4) & 1) * 8) * STRD + ((lane >> 3) & 1) * 4;
    // V (transposed) lane base
    const int vlb = (lane & 15) * STRD + ((lane >> 4) << 2);

    for (int kt = 0; kt < nkt; kt++) {
        const unsigned* K = Ks + (kt & 1) * TBUF;
        const unsigned* V = Vs + (kt & 1) * TBUF;
        if (kt + 1 < nkt) {
            const int nb = (kt + 1) & 1;
            const size_t kb0 = (size_t)(kt + 1) * 64;
#pragma unroll
            for (int i = 0; i < 4; i++) {
                int id = tid + i * 128;
                int r = id >> 3, c = (id & 7) * 4;
                cp16(Ks + nb * TBUF + r * STRD + c, gk + (kb0 + r) * 32 + c);
                cp16(Vs + nb * TBUF + r * STRD + c, gv + (kb0 + r) * 32 + c);
            }
            CP_COMMIT();
            asm volatile("cp.async.wait_group 1;" ::: "memory");
        } else {
            asm volatile("cp.async.wait_group 0;" ::: "memory");
        }
        __syncthreads();

        // S(log2 domain) = Qscaled K^T ; fragments via ldmatrix
        float sacc[8][4];
#pragma unroll
        for (int nt = 0; nt < 8; nt++) {
            sacc[nt][0] = 0.f; sacc[nt][1] = 0.f; sacc[nt][2] = 0.f; sacc[nt][3] = 0.f;
        }
#pragma unroll
        for (int s = 0; s < 4; s++) {
            unsigned qa0, qa1, qa2, qa3;
            ldm4(qa0, qa1, qa2, qa3, Qs + rowbase * STRD + s * 8 + qlb);
#pragma unroll
            for (int np = 0; np < 4; np++) {
                unsigned b0, b1, b2, b3;
                ldm4(b0, b1, b2, b3, K + np * 16 * STRD + s * 8 + klb);
                mma16(sacc[2 * np][0], sacc[2 * np][1], sacc[2 * np][2], sacc[2 * np][3],
                      qa0, qa1, qa2, qa3, b0, b1);
                mma16(sacc[2 * np + 1][0], sacc[2 * np + 1][1],
                      sacc[2 * np + 1][2], sacc[2 * np + 1][3],
                      qa0, qa1, qa2, qa3, b2, b3);
            }
        }

        // causal mask on the diagonal tile only; row max
        float rmax0 = -1e30f, rmax1 = -1e30f;
        if (kt == nkt - 1) {
            const int kbase = kt * 64;
#pragma unroll
            for (int nt = 0; nt < 8; nt++) {
                int c0 = kbase + nt * 8 + tig * 2;
                float v0 = sacc[nt][0] + ((c0     > qrow0) ? -6e8f : 0.f);
                float v1 = sacc[nt][1] + ((c0 + 1 > qrow0) ? -6e8f : 0.f);
                float v2 = sacc[nt][2] + ((c0     > qrow1) ? -6e8f : 0.f);
                float v3 = sacc[nt][3] + ((c0 + 1 > qrow1) ? -6e8f : 0.f);
                sacc[nt][0] = v0; sacc[nt][1] = v1; sacc[nt][2] = v2; sacc[nt][3] = v3;
                rmax0 = fmaxf(rmax0, fmaxf(v0, v1));
                rmax1 = fmaxf(rmax1, fmaxf(v2, v3));
            }
        } else {
#pragma unroll
            for (int nt = 0; nt < 8; nt++) {
                rmax0 = fmaxf(rmax0, fmaxf(sacc[nt][0], sacc[nt][1]));
                rmax1 = fmaxf(rmax1, fmaxf(sacc[nt][2], sacc[nt][3]));
            }
        }
        rmax0 = fmaxf(rmax0, __shfl_xor_sync(0xffffffffu, rmax0, 1));
        rmax0 = fmaxf(rmax0, __shfl_xor_sync(0xffffffffu, rmax0, 2));
        rmax1 = fmaxf(rmax1, __shfl_xor_sync(0xffffffffu, rmax1, 1));
        rmax1 = fmaxf(rmax1, __shfl_xor_sync(0xffffffffu, rmax1, 2));

        // rescale only when the running max moves
        if (__any_sync(0xffffffffu, (rmax0 > mrow0) | (rmax1 > mrow1))) {
            float mnew0 = fmaxf(mrow0, rmax0);
            float mnew1 = fmaxf(mrow1, rmax1);
            float alpha0 = ex2f(mrow0 - mnew0);
            float alpha1 = ex2f(mrow1 - mnew1);
            lrow0 *= alpha0; lrow1 *= alpha1;
#pragma unroll
            for (int nt = 0; nt < 8; nt++) {
                Oa[nt][0] *= alpha0; Oa[nt][1] *= alpha0;
                Oa[nt][2] *= alpha1; Oa[nt][3] *= alpha1;
            }
            mrow0 = mnew0; mrow1 = mnew1;
        }

        // P = 2^(w - m) packed fp16 (== PV A-fragment)
        unsigned plo[8], phi[8];
#pragma unroll
        for (int nt = 0; nt < 8; nt++) {
            plo[nt] = h2ex2(packh2(sacc[nt][0] - mrow0, sacc[nt][1] - mrow0));
            phi[nt] = h2ex2(packh2(sacc[nt][2] - mrow1, sacc[nt][3] - mrow1));
        }

        // row sums via ones-column MMA (exact f32 sums of the SAME fp16 P)
        float rs0 = 0.f, rsx = 0.f, rs1 = 0.f, rsy = 0.f;
#pragma unroll
        for (int s = 0; s < 4; s++)
            mma16(rs0, rsx, rs1, rsy,
                  plo[2 * s], phi[2 * s], plo[2 * s + 1], phi[2 * s + 1],
                  H2ONES, H2ONES);
        lrow0 += rs0;
        lrow1 += rs1;

        // O += P V
#pragma unroll
        for (int s = 0; s < 4; s++) {
            unsigned a0 = plo[2 * s], a1 = phi[2 * s];
            unsigned a2 = plo[2 * s + 1], a3 = phi[2 * s + 1];
            const unsigned* vrow = V + s * 16 * STRD + vlb;
#pragma unroll
            for (int ntp = 0; ntp < 4; ntp++) {
                unsigned b0, b1, b2, b3;
                ldmT4(b0, b1, b2, b3, vrow + ntp * 8);
                mma16(Oa[2 * ntp][0],     Oa[2 * ntp][1],     Oa[2 * ntp][2],     Oa[2 * ntp][3],
                      a0, a1, a2, a3, b0, b1);
                mma16(Oa[2 * ntp + 1][0], Oa[2 * ntp + 1][1], Oa[2 * ntp + 1][2], Oa[2 * ntp + 1][3],
                      a0, a1, a2, a3, b2, b3);
            }
        }
        __syncthreads();
    }

    float inv0 = 1.f / lrow0;
    float inv1 = 1.f / lrow1;
    float* o0 = out + ((size_t)(b * SEQ + qrow0)) * DMODEL + h * HDIM;
    float* o1 = out + ((size_t)(b * SEQ + qrow1)) * DMODEL + h * HDIM;
#pragma unroll
    for (int nt = 0; nt < 8; nt++) {
        int dh = nt * 8 + tig * 2;
        *(float2*)(o0 + dh) = make_float2(Oa[nt][0] * inv0, Oa[nt][1] * inv0);
        *(float2*)(o1 + dh) = make_float2(Oa[nt][2] * inv1, Oa[nt][3] * inv1);
    }
}

// ---------------------------------------------------------------------------
// Launch
// ---------------------------------------------------------------------------
extern "C" void kernel_launch(void* const* d_in, const int* in_sizes, int n_in,
                              void* d_out, int out_size) {
    (void)in_sizes; (void)n_in; (void)out_size;
    const float* x  = (const float*)d_in[0];
    const float* Wq = (const float*)d_in[1];
    const float* bq = (const float*)d_in[2];
    const float* Wk = (const float*)d_in[3];
    const float* bk = (const float*)d_in[4];
    const float* Wv = (const float*)d_in[5];
    const float* bv = (const float*)d_in[6];
    float* out = (float*)d_out;

    pack_all<<<1792, 256>>>(x, Wq, Wk, Wv);

    cudaFuncSetAttribute(qkv_h, cudaFuncAttributeMaxDynamicSharedMemorySize,
                         QKV_SMEM_BYTES);
    dim3 gq(24, 32, 1);
    qkv_h<<<gq, 256, QKV_SMEM_BYTES>>>(bq, bk, bv);

    cudaFuncSetAttribute(attn_kernel, cudaFuncAttributeMaxDynamicSharedMemorySize,
                         ATT_SMEM_BYTES);
    dim3 ga(32, 16, 2);
    attn_kernel<<<ga, 128, ATT_SMEM_BYTES>>>(out);
}

// round 17
// speedup vs baseline: 1.1490x; 1.0610x over previous
#include <cuda_runtime.h>
#include <cuda_fp16.h>
#include <cstdint>

// ---------------------------------------------------------------------------
//   x [2,2048,1024] f32, Wq/Wk/Wv [1024,1024] f32 ([k][n]), bq/bk/bv [1024]
//   out [2,2048,1024] f32 = causal MHA, 16 heads, head_dim 64,
//   softmax((QK^T + mask)/8)
// fp16 datapath; legacy mma.m16n8k16 (harness compiles compute_103, no 'a').
// Q pre-scaled by 0.125*log2(e): QK^T lands directly in the log2 domain.
// ---------------------------------------------------------------------------

#define NHEADS 16
#define HDIM   64
#define SEQ    2048
#define BATCH  2
#define DMODEL 1024

__device__ unsigned g_xh[4096 * 512];            // x   [m][k-words], plain
__device__ unsigned g_wt[3 * 1024 * 512];        // W^T [mat][n][k-words], plain
__device__ unsigned g_qh[BATCH * NHEADS * SEQ * 32];  // [b,h,s][dh-words], plain, pre-scaled
__device__ unsigned g_kh[BATCH * NHEADS * SEQ * 32];  // plain
__device__ unsigned g_vh[BATCH * NHEADS * SEQ * 32];  // plain

// ---------------------------------------------------------------------------
// helpers
// ---------------------------------------------------------------------------
__device__ __forceinline__ unsigned packh2(float lo, float hi) {
    __half2 h = __floats2half2_rn(lo, hi);
    return *(unsigned*)&h;
}

__device__ __forceinline__ float ex2f(float x) {
    float r; asm("ex2.approx.f32 %0, %1;" : "=f"(r) : "f"(x)); return r;
}
__device__ __forceinline__ unsigned h2ex2(unsigned x) {
    unsigned r; asm("ex2.approx.f16x2 %0, %1;" : "=r"(r) : "r"(x)); return r;
}

__device__ __forceinline__ void mma16(float& d0, float& d1, float& d2, float& d3,
                                      unsigned a0, unsigned a1, unsigned a2, unsigned a3,
                                      unsigned b0, unsigned b1) {
    asm("mma.sync.aligned.m16n8k16.row.col.f32.f16.f16.f32 "
        "{%0,%1,%2,%3},{%4,%5,%6,%7},{%8,%9},{%0,%1,%2,%3};"
        : "+f"(d0), "+f"(d1), "+f"(d2), "+f"(d3)
        : "r"(a0), "r"(a1), "r"(a2), "r"(a3), "r"(b0), "r"(b1));
}

__device__ __forceinline__ void ldm4(unsigned& r0, unsigned& r1,
                                     unsigned& r2, unsigned& r3, const void* p) {
    unsigned a = (unsigned)__cvta_generic_to_shared(p);
    asm volatile("ldmatrix.sync.aligned.m8n8.x4.shared.b16 {%0,%1,%2,%3}, [%4];"
                 : "=r"(r0), "=r"(r1), "=r"(r2), "=r"(r3) : "r"(a));
}
__device__ __forceinline__ void ldmT4(unsigned& r0, unsigned& r1,
                                      unsigned& r2, unsigned& r3, const void* p) {
    unsigned a = (unsigned)__cvta_generic_to_shared(p);
    asm volatile("ldmatrix.sync.aligned.m8n8.x4.trans.shared.b16 {%0,%1,%2,%3}, [%4];"
                 : "=r"(r0), "=r"(r1), "=r"(r2), "=r"(r3) : "r"(a));
}

__device__ __forceinline__ void cp16(void* smem, const void* gmem) {
    unsigned s = (unsigned)__cvta_generic_to_shared(smem);
    asm volatile("cp.async.ca.shared.global [%0], [%1], 16;" :: "r"(s), "l"(gmem));
}
#define CP_COMMIT() asm volatile("cp.async.commit_group;" ::: "memory")

// ---------------------------------------------------------------------------
// Pre-pass (single launch): pack x and W^T -> fp16 pair-words, plain order
// ---------------------------------------------------------------------------
__global__ void pack_all(const float* __restrict__ x,
                         const float* __restrict__ Wq,
                         const float* __restrict__ Wk,
                         const float* __restrict__ Wv) {
    if (blockIdx.x < 1024) {
        int idx = blockIdx.x * 256 + threadIdx.x;
        const float4* src = (const float4*)x + (size_t)idx * 4;
        float4 f0 = src[0], f1 = src[1], f2 = src[2], f3 = src[3];
        uint4* dst = (uint4*)(g_xh + (size_t)idx * 8);
        dst[0] = make_uint4(packh2(f0.x, f0.y), packh2(f0.z, f0.w),
                            packh2(f1.x, f1.y), packh2(f1.z, f1.w));
        dst[1] = make_uint4(packh2(f2.x, f2.y), packh2(f2.z, f2.w),
                            packh2(f3.x, f3.y), packh2(f3.z, f3.w));
    } else {
        int id  = (blockIdx.x - 1024) * 256 + threadIdx.x;
        int mat = id >> 16;
        int rem = id & 65535;
        int grp = rem >> 10;
        int n   = rem & 1023;
        const float* W = (mat == 0) ? Wq : ((mat == 1) ? Wk : Wv);
        int k0 = grp * 16;
        unsigned w[8];
#pragma unroll
        for (int j = 0; j < 8; j++)
            w[j] = packh2(W[(size_t)(k0 + 2 * j) * DMODEL + n],
                          W[(size_t)(k0 + 2 * j + 1) * DMODEL + n]);
        uint4* dst = (uint4*)(g_wt + ((size_t)mat << 19) + (size_t)n * 512 + grp * 8);
        dst[0] = make_uint4(w[0], w[1], w[2], w[3]);
        dst[1] = make_uint4(w[4], w[5], w[6], w[7]);
    }
}

// ---------------------------------------------------------------------------
// Kernel 1: QKV projection, fp16 m16n8k16, ldmatrix fragments
//   grid (24, 64): x = mat*8 + ntile (BN=128), y = m-tile (BM=64), BK=32
//   block 128 (4 warps 2Mx2N, warp tile 32x64), 4 CTAs/SM,
//   2-stage cp.async double buffer.
// ---------------------------------------------------------------------------
#define QS 36                       // stride: 4r mod 32 distinct -> LDSM CF
#define QKV_STAGEW ((64 + 128) * QS)
#define QKV_SMEM_BYTES (2 * QKV_STAGEW * 4)   // 54 KB

__global__ __launch_bounds__(128, 4)
void qkv_h(const float* __restrict__ bq, const float* __restrict__ bk,
           const float* __restrict__ bv) {
    extern __shared__ unsigned qsm[];

    const int tid  = threadIdx.x;
    const int wid  = tid >> 5;
    const int lane = tid & 31;
    const int g    = lane >> 2;
    const int tig  = lane & 3;

    const int mat = blockIdx.x >> 3;
    const int n0  = (blockIdx.x & 7) * 128;
    const int m0  = blockIdx.y * 64;

    const unsigned* Asrc = g_xh + (size_t)m0 * 512;
    const unsigned* Bsrc = g_wt + ((size_t)mat << 19) + (size_t)n0 * 512;
    const float* bias = (mat == 0) ? bq : ((mat == 1) ? bk : bv);

    const int warpM = (wid & 1) * 32;
    const int warpN = (wid >> 1) * 64;

    float acc[2][8][4];
#pragma unroll
    for (int mt = 0; mt < 2; mt++)
#pragma unroll
        for (int nt = 0; nt < 8; nt++)
#pragma unroll
            for (int j = 0; j < 4; j++) acc[mt][nt][j] = 0.f;

    // ldmatrix lane bases (shared layout: [row][QS words])
    const int alb = ((lane & 7) + ((lane >> 3) & 1) * 8) * QS + ((lane >> 4) & 1) * 4;
    const int blb = ((lane & 7) + ((lane >> 4) & 1) * 8) * QS + ((lane >> 3) & 1) * 4;

    // staging: A rows 0-63 at offset 0, B rows 0-127 at offset 64*QS
#define QKV_STAGE(buf, kw)                                                      \
    do {                                                                        \
        unsigned* S_ = qsm + (buf) * QKV_STAGEW;                                \
        _Pragma("unroll")                                                       \
        for (int i_ = 0; i_ < 2; i_++) {                                        \
            int id_ = tid + i_ * 128;                                           \
            int r_ = id_ >> 2, c_ = (id_ & 3) * 4;                              \
            cp16(&S_[r_ * QS + c_], Asrc + (size_t)r_ * 512 + (kw) + c_);       \
        }                                                                       \
        _Pragma("unroll")                                                       \
        for (int i_ = 0; i_ < 4; i_++) {                                        \
            int id_ = tid + i_ * 128;                                           \
            int r_ = id_ >> 2, c_ = (id_ & 3) * 4;                              \
            cp16(&S_[64 * QS + r_ * QS + c_], Bsrc + (size_t)r_ * 512 + (kw) + c_); \
        }                                                                       \
    } while (0)

    QKV_STAGE(0, 0);
    CP_COMMIT();

    for (int it = 0; it < 32; it++) {
        if (it + 1 < 32) {
            QKV_STAGE((it + 1) & 1, (it + 1) * 16);
            CP_COMMIT();
            asm volatile("cp.async.wait_group 1;" ::: "memory");
        } else {
            asm volatile("cp.async.wait_group 0;" ::: "memory");
        }
        __syncthreads();

        const unsigned* A = qsm + (it & 1) * QKV_STAGEW;
        const unsigned* B = A + 64 * QS;
#pragma unroll
        for (int s = 0; s < 2; s++) {
            unsigned a[2][4];
#pragma unroll
            for (int mt = 0; mt < 2; mt++)
                ldm4(a[mt][0], a[mt][1], a[mt][2], a[mt][3],
                     A + (warpM + mt * 16) * QS + s * 8 + alb);
#pragma unroll
            for (int np = 0; np < 4; np++) {
                unsigned b0, b1, b2, b3;
                ldm4(b0, b1, b2, b3, B + (warpN + np * 16) * QS + s * 8 + blb);
#pragma unroll
                for (int mt = 0; mt < 2; mt++) {
                    mma16(acc[mt][2 * np][0], acc[mt][2 * np][1],
                          acc[mt][2 * np][2], acc[mt][2 * np][3],
                          a[mt][0], a[mt][1], a[mt][2], a[mt][3], b0, b1);
                    mma16(acc[mt][2 * np + 1][0], acc[mt][2 * np + 1][1],
                          acc[mt][2 * np + 1][2], acc[mt][2 * np + 1][3],
                          a[mt][0], a[mt][1], a[mt][2], a[mt][3], b2, b3);
                }
            }
        }
        __syncthreads();
    }

    // epilogue: (+bias)*scale, pack fp16 pairs, plain [B,H,S][dh-words]
    unsigned* dst = (mat == 0) ? g_qh : ((mat == 1) ? g_kh : g_vh);
    const float scl = (mat == 0) ? 0.18033688011112042f : 1.0f;  // 0.125*log2e
#pragma unroll
    for (int mt = 0; mt < 2; mt++) {
        int rr0 = m0 + warpM + mt * 16 + g;
        int rr1 = rr0 + 8;
        int bb_ = rr0 >> 11;
        int s0 = rr0 & 2047, s1 = rr1 & 2047;
#pragma unroll
        for (int nt = 0; nt < 8; nt++) {
            int col = n0 + warpN + nt * 8 + tig * 2;
            float bv0 = bias[col], bv1 = bias[col + 1];
            int pos = (col & 63) >> 1;
            int hh = col >> 6;
            size_t base = (size_t)(bb_ * NHEADS + hh) * SEQ;
            dst[(base + s0) * 32 + pos] =
                packh2((acc[mt][nt][0] + bv0) * scl, (acc[mt][nt][1] + bv1) * scl);
            dst[(base + s1) * 32 + pos] =
                packh2((acc[mt][nt][2] + bv0) * scl, (acc[mt][nt][3] + bv1) * scl);
        }
    }
}

// ---------------------------------------------------------------------------
// Kernel 2: causal flash attention, fp16 m16n8k16 (unchanged from R16)
// ---------------------------------------------------------------------------
#define STRD 36
#define TBUF (64 * STRD)
#define ATT_SMEM_WORDS (5 * TBUF)
#define ATT_SMEM_BYTES (ATT_SMEM_WORDS * 4)
#define H2ONES 0x3C003C00u

__global__ __launch_bounds__(128, 4)
void attn_kernel(float* __restrict__ out) {
    extern __shared__ unsigned smem[];
    unsigned* Qs = smem;
    unsigned* Ks = Qs + TBUF;
    unsigned* Vs = Ks + 2 * TBUF;

    const int tid  = threadIdx.x;
    const int wid  = tid >> 5;
    const int lane = tid & 31;
    const int tig  = lane & 3;

    const int b  = blockIdx.z;
    const int h  = blockIdx.y;
    const int qt = (int)gridDim.x - 1 - (int)blockIdx.x;
    const int q0 = qt * 64;

    const size_t hw = (size_t)(b * NHEADS + h) * SEQ * 32;
    const unsigned* gq = g_qh + hw;
    const unsigned* gk = g_kh + hw;
    const unsigned* gv = g_vh + hw;

    const int nkt = qt + 1;

#pragma unroll
    for (int i = 0; i < 4; i++) {
        int id = tid + i * 128;
        int r = id >> 3, c = (id & 7) * 4;
        cp16(Ks + r * STRD + c, gk + (size_t)r * 32 + c);
        cp16(Vs + r * STRD + c, gv + (size_t)r * 32 + c);
    }
    CP_COMMIT();

#pragma unroll
    for (int i = 0; i < 4; i++) {
        int id = tid + i * 128;
        int r = id >> 3, c = (id & 7) * 4;
        *(uint4*)(Qs + r * STRD + c) = *(const uint4*)(gq + (size_t)(q0 + r) * 32 + c);
    }

    float Oa[8][4];
#pragma unroll
    for (int nt = 0; nt < 8; nt++)
#pragma unroll
        for (int j = 0; j < 4; j++) Oa[nt][j] = 0.f;

    float mrow0 = -1e30f, mrow1 = -1e30f, lrow0 = 0.f, lrow1 = 0.f;
    const int rowbase = wid * 16;
    const int qrow0 = q0 + rowbase + (lane >> 2);
    const int qrow1 = qrow0 + 8;

    const int qlb = ((lane & 7) + ((lane >> 3) & 1) * 8) * STRD + ((lane >> 4) & 1) * 4;
    const int klb = ((lane & 7) + ((lane >> 4) & 1) * 8) * STRD + ((lane >> 3) & 1) * 4;
    const int vlb = (lane & 15) * STRD + ((lane >> 4) << 2);

    for (int kt = 0; kt < nkt; kt++) {
        const unsigned* K = Ks + (kt & 1) * TBUF;
        const unsigned* V = Vs + (kt & 1) * TBUF;
        if (kt + 1 < nkt) {
            const int nb = (kt + 1) & 1;
            const size_t kb0 = (size_t)(kt + 1) * 64;
#pragma unroll
            for (int i = 0; i < 4; i++) {
                int id = tid + i * 128;
                int r = id >> 3, c = (id & 7) * 4;
                cp16(Ks + nb * TBUF + r * STRD + c, gk + (kb0 + r) * 32 + c);
                cp16(Vs + nb * TBUF + r * STRD + c, gv + (kb0 + r) * 32 + c);
            }
            CP_COMMIT();
            asm volatile("cp.async.wait_group 1;" ::: "memory");
        } else {
            asm volatile("cp.async.wait_group 0;" ::: "memory");
        }
        __syncthreads();

        float sacc[8][4];
#pragma unroll
        for (int nt = 0; nt < 8; nt++) {
            sacc[nt][0] = 0.f; sacc[nt][1] = 0.f; sacc[nt][2] = 0.f; sacc[nt][3] = 0.f;
        }
#pragma unroll
        for (int s = 0; s < 4; s++) {
            unsigned qa0, qa1, qa2, qa3;
            ldm4(qa0, qa1, qa2, qa3, Qs + rowbase * STRD + s * 8 + qlb);
#pragma unroll
            for (int np = 0; np < 4; np++) {
                unsigned b0, b1, b2, b3;
                ldm4(b0, b1, b2, b3, K + np * 16 * STRD + s * 8 + klb);
                mma16(sacc[2 * np][0], sacc[2 * np][1], sacc[2 * np][2], sacc[2 * np][3],
                      qa0, qa1, qa2, qa3, b0, b1);
                mma16(sacc[2 * np + 1][0], sacc[2 * np + 1][1],
                      sacc[2 * np + 1][2], sacc[2 * np + 1][3],
                      qa0, qa1, qa2, qa3, b2, b3);
            }
        }

        float rmax0 = -1e30f, rmax1 = -1e30f;
        if (kt == nkt - 1) {
            const int kbase = kt * 64;
#pragma unroll
            for (int nt = 0; nt < 8; nt++) {
                int c0 = kbase + nt * 8 + tig * 2;
                float v0 = sacc[nt][0] + ((c0     > qrow0) ? -6e8f : 0.f);
                float v1 = sacc[nt][1] + ((c0 + 1 > qrow0) ? -6e8f : 0.f);
                float v2 = sacc[nt][2] + ((c0     > qrow1) ? -6e8f : 0.f);
                float v3 = sacc[nt][3] + ((c0 + 1 > qrow1) ? -6e8f : 0.f);
                sacc[nt][0] = v0; sacc[nt][1] = v1; sacc[nt][2] = v2; sacc[nt][3] = v3;
                rmax0 = fmaxf(rmax0, fmaxf(v0, v1));
                rmax1 = fmaxf(rmax1, fmaxf(v2, v3));
            }
        } else {
#pragma unroll
            for (int nt = 0; nt < 8; nt++) {
                rmax0 = fmaxf(rmax0, fmaxf(sacc[nt][0], sacc[nt][1]));
                rmax1 = fmaxf(rmax1, fmaxf(sacc[nt][2], sacc[nt][3]));
            }
        }
        rmax0 = fmaxf(rmax0, __shfl_xor_sync(0xffffffffu, rmax0, 1));
        rmax0 = fmaxf(rmax0, __shfl_xor_sync(0xffffffffu, rmax0, 2));
        rmax1 = fmaxf(rmax1, __shfl_xor_sync(0xffffffffu, rmax1, 1));
        rmax1 = fmaxf(rmax1, __shfl_xor_sync(0xffffffffu, rmax1, 2));

        if (__any_sync(0xffffffffu, (rmax0 > mrow0) | (rmax1 > mrow1))) {
            float mnew0 = fmaxf(mrow0, rmax0);
            float mnew1 = fmaxf(mrow1, rmax1);
            float alpha0 = ex2f(mrow0 - mnew0);
            float alpha1 = ex2f(mrow1 - mnew1);
            lrow0 *= alpha0; lrow1 *= alpha1;
#pragma unroll
            for (int nt = 0; nt < 8; nt++) {
                Oa[nt][0] *= alpha0; Oa[nt][1] *= alpha0;
                Oa[nt][2] *= alpha1; Oa[nt][3] *= alpha1;
            }
            mrow0 = mnew0; mrow1 = mnew1;
        }

        unsigned plo[8], phi[8];
#pragma unroll
        for (int nt = 0; nt < 8; nt++) {
            plo[nt] = h2ex2(packh2(sacc[nt][0] - mrow0, sacc[nt][1] - mrow0));
            phi[nt] = h2ex2(packh2(sacc[nt][2] - mrow1, sacc[nt][3] - mrow1));
        }

        float rs0 = 0.f, rsx = 0.f, rs1 = 0.f, rsy = 0.f;
#pragma unroll
        for (int s = 0; s < 4; s++)
            mma16(rs0, rsx, rs1, rsy,
                  plo[2 * s], phi[2 * s], plo[2 * s + 1], phi[2 * s + 1],
                  H2ONES, H2ONES);
        lrow0 += rs0;
        lrow1 += rs1;

#pragma unroll
        for (int s = 0; s < 4; s++) {
            unsigned a0 = plo[2 * s], a1 = phi[2 * s];
            unsigned a2 = plo[2 * s + 1], a3 = phi[2 * s + 1];
            const unsigned* vrow = V + s * 16 * STRD + vlb;
#pragma unroll
            for (int ntp = 0; ntp < 4; ntp++) {
                unsigned b0, b1, b2, b3;
                ldmT4(b0, b1, b2, b3, vrow + ntp * 8);
                mma16(Oa[2 * ntp][0],     Oa[2 * ntp][1],     Oa[2 * ntp][2],     Oa[2 * ntp][3],
                      a0, a1, a2, a3, b0, b1);
                mma16(Oa[2 * ntp + 1][0], Oa[2 * ntp + 1][1], Oa[2 * ntp + 1][2], Oa[2 * ntp + 1][3],
                      a0, a1, a2, a3, b2, b3);
            }
        }
        __syncthreads();
    }

    float inv0 = 1.f / lrow0;
    float inv1 = 1.f / lrow1;
    float* o0 = out + ((size_t)(b * SEQ + qrow0)) * DMODEL + h * HDIM;
    float* o1 = out + ((size_t)(b * SEQ + qrow1)) * DMODEL + h * HDIM;
#pragma unroll
    for (int nt = 0; nt < 8; nt++) {
        int dh = nt * 8 + tig * 2;
        *(float2*)(o0 + dh) = make_float2(Oa[nt][0] * inv0, Oa[nt][1] * inv0);
        *(float2*)(o1 + dh) = make_float2(Oa[nt][2] * inv1, Oa[nt][3] * inv1);
    }
}

// ---------------------------------------------------------------------------
// Launch
// ---------------------------------------------------------------------------
extern "C" void kernel_launch(void* const* d_in, const int* in_sizes, int n_in,
                              void* d_out, int out_size) {
    (void)in_sizes; (void)n_in; (void)out_size;
    const float* x  = (const float*)d_in[0];
    const float* Wq = (const float*)d_in[1];
    const float* bq = (const float*)d_in[2];
    const float* Wk = (const float*)d_in[3];
    const float* bk = (const float*)d_in[4];
    const float* Wv = (const float*)d_in[5];
    const float* bv = (const float*)d_in[6];
    float* out = (float*)d_out;

    pack_all<<<1792, 256>>>(x, Wq, Wk, Wv);

    cudaFuncSetAttribute(qkv_h, cudaFuncAttributeMaxDynamicSharedMemorySize,
                         QKV_SMEM_BYTES);
    dim3 gq(24, 64, 1);
    qkv_h<<<gq, 128, QKV_SMEM_BYTES>>>(bq, bk, bv);

    cudaFuncSetAttribute(attn_kernel, cudaFuncAttributeMaxDynamicSharedMemorySize,
                         ATT_SMEM_BYTES);
    dim3 ga(32, 16, 2);
    attn_kernel<<<ga, 128, ATT_SMEM_BYTES>>>(out);
}